// round 1
// baseline (speedup 1.0000x reference)
#include <cuda_runtime.h>
#include <cuda_bf16.h>
#include <math.h>

// ---------------------------------------------------------------------------
// MolecularGNN fully fused:  embed -> L_HID gnn layers -> mol sum -> MLP -> out
// Everything is block-diagonal per molecule (edges stay inside a molecule's
// S-atom block), so one CTA handles G molecules end-to-end in shared memory.
// Preprocessing per launch: counting-sort edges by dst node into a CSR of
// u8 local-src indices, and transpose the weight matrices.
// ---------------------------------------------------------------------------

#define MAX_T   524289            // max atoms + 1 (for csr_off[T])
#define MAX_E   2200000           // max edges
#define MAX_LAY 8                 // L_HID + L_OUT
#define TILE_ROWS 128             // padded atom rows per CTA

// __device__ scratch (no allocations allowed)
__device__ unsigned      g_deg[MAX_T];
__device__ unsigned      g_off[MAX_T];       // exclusive prefix, plus [T]=E
__device__ unsigned      g_cur[MAX_T];
__device__ unsigned char g_csr[MAX_E];       // local src index per edge, CSR by dst
__device__ unsigned      g_part[1024];
__device__ float         g_Wt[MAX_LAY * 4096]; // transposed 64x64 weights

// ---------------------------------------------------------------------------

__global__ void zero_kernel(int T) {
    int i = blockIdx.x * blockDim.x + threadIdx.x;
    if (i < T) { g_deg[i] = 0u; g_cur[i] = 0u; }
}

__global__ void hist_kernel(const int* __restrict__ dst, int E) {
    int e = blockIdx.x * blockDim.x + threadIdx.x;
    if (e < E) atomicAdd(&g_deg[dst[e]], 1u);
}

// per-1024-chunk exclusive scan, chunk totals to g_part
__global__ void scan1_kernel(int T) {
    __shared__ unsigned wsum[8];
    int t = threadIdx.x, lane = t & 31, wid = t >> 5;
    int base = blockIdx.x * 1024 + t * 4;
    unsigned vals[4];
#pragma unroll
    for (int i = 0; i < 4; i++) { int idx = base + i; vals[i] = (idx < T) ? g_deg[idx] : 0u; }
    unsigned tot = vals[0] + vals[1] + vals[2] + vals[3];
    unsigned inc = tot;
#pragma unroll
    for (int o = 1; o < 32; o <<= 1) { unsigned n = __shfl_up_sync(0xffffffffu, inc, o); if (lane >= o) inc += n; }
    if (lane == 31) wsum[wid] = inc;
    __syncthreads();
    if (wid == 0) {
        unsigned w = (lane < 8) ? wsum[lane] : 0u;
#pragma unroll
        for (int o = 1; o < 8; o <<= 1) { unsigned n = __shfl_up_sync(0xffffffffu, w, o); if (lane >= o) w += n; }
        if (lane < 8) wsum[lane] = w;
    }
    __syncthreads();
    unsigned run = ((wid > 0) ? wsum[wid - 1] : 0u) + inc - tot;
#pragma unroll
    for (int i = 0; i < 4; i++) { int idx = base + i; if (idx < T) g_off[idx] = run; run += vals[i]; }
    if (t == 255) g_part[blockIdx.x] = wsum[7];
}

// single-block exclusive scan of g_part[0..NB)
__global__ void scan2_kernel(int NB) {
    __shared__ unsigned wsum[8];
    __shared__ unsigned carry_sh;
    int t = threadIdx.x, lane = t & 31, wid = t >> 5;
    if (t == 0) carry_sh = 0u;
    __syncthreads();
    for (int start = 0; start < NB; start += 256) {
        unsigned carry = carry_sh;
        int idx = start + t;
        unsigned v = (idx < NB) ? g_part[idx] : 0u;
        unsigned inc = v;
#pragma unroll
        for (int o = 1; o < 32; o <<= 1) { unsigned n = __shfl_up_sync(0xffffffffu, inc, o); if (lane >= o) inc += n; }
        if (lane == 31) wsum[wid] = inc;
        __syncthreads();
        if (wid == 0) {
            unsigned w = (lane < 8) ? wsum[lane] : 0u;
#pragma unroll
            for (int o = 1; o < 8; o <<= 1) { unsigned n = __shfl_up_sync(0xffffffffu, w, o); if (lane >= o) w += n; }
            if (lane < 8) wsum[lane] = w;
        }
        __syncthreads();
        unsigned excl = carry + ((wid > 0) ? wsum[wid - 1] : 0u) + inc - v;
        if (idx < NB) g_part[idx] = excl;
        __syncthreads();
        if (t == 0) carry_sh = carry + wsum[7];
        __syncthreads();
    }
}

__global__ void scan3_kernel(int T, int E) {
    unsigned add = g_part[blockIdx.x];
    int base = blockIdx.x * 1024;
    for (int i = threadIdx.x; i < 1024; i += 256) {
        int idx = base + i;
        if (idx < T) g_off[idx] += add;
    }
    if (blockIdx.x == 0 && threadIdx.x == 0) g_off[T] = (unsigned)E;
}

__global__ void scatter_kernel(const int* __restrict__ src, const int* __restrict__ dst,
                               int E, int S) {
    int e = blockIdx.x * blockDim.x + threadIdx.x;
    if (e < E) {
        int d = dst[e];
        unsigned pos = g_off[d] + atomicAdd(&g_cur[d], 1u);
        int s = src[e];
        g_csr[pos] = (unsigned char)(s - (s / S) * S);   // local index in molecule
    }
}

// transpose all 64x64 weight matrices (coalesced write, L2-hit strided read)
__global__ void wtrans_kernel(const float* __restrict__ Wfp, const float* __restrict__ Wout,
                              int LH) {
    int b = blockIdx.x;
    const float* Ws = (b < LH) ? (Wfp + b * 4096) : (Wout + (b - LH) * 4096);
    float* o = g_Wt + b * 4096;
    for (int i = threadIdx.x; i < 4096; i += blockDim.x) {
        int k = i >> 6, j = i & 63;
        o[i] = Ws[j * 64 + k];        // Wt[k][j] = W[j][k]
    }
}

// ---------------------------------------------------------------------------
// The fused kernel. One CTA: G molecules (G*S <= 128 atoms).
// smem layout (floats): v[128*64] | h[128*64] | w[64*64] | inv[128]
// ---------------------------------------------------------------------------
__global__ __launch_bounds__(256)
void gnn_fused_kernel(const int* __restrict__ fp,
                      const float* __restrict__ emb,
                      const float* __restrict__ b_fp,
                      const float* __restrict__ b_out,
                      const float* __restrict__ wprop,
                      const float* __restrict__ bprop,
                      float* __restrict__ out,
                      int S, int G, int M, int LH, int LO) {
    extern __shared__ float sm[];
    float* v_sh  = sm;                 // 8192
    float* h_sh  = sm + 8192;          // 8192
    float* w_sh  = sm + 16384;         // 4096
    float* inv_sh = sm + 20480;        // 128

    const int t = threadIdx.x;
    const int molBase = blockIdx.x * G;
    const int Ga = min(G, M - molBase);     // molecules in this block
    if (Ga <= 0) return;
    const int GA = Ga * S;                  // valid atom rows
    const int atomBase = molBase * S;

    const int tc = t & 15, trg = t >> 4;    // gemm: 16 col-threads x 16 row-groups
    const int c0 = tc * 4, r0 = trg * 8;
    const int tj = t & 63, rg = t >> 6;     // agg: 64 cols x 4 row-groups
    const int warp = t >> 5, lane = t & 31;

    // ---- load embeddings into v_sh (padded rows zeroed) ----
    for (int idx = t; idx < GA * 64; idx += 256) {
        int r = idx >> 6, j = idx & 63;
        int f = fp[atomBase + r];
        v_sh[idx] = emb[f * 64 + j];
    }
    for (int idx = GA * 64 + t; idx < TILE_ROWS * 64; idx += 256) v_sh[idx] = 0.f;

    // ---- GNN layers ----
    for (int l = 0; l < LH; l++) {
        __syncthreads();
        // stage transposed weights
        {
            const float4* ws = (const float4*)(g_Wt + l * 4096);
            float4* wd = (float4*)w_sh;
            for (int i = t; i < 1024; i += 256) wd[i] = ws[i];
        }
        float bias[4];
        *(float4*)bias = *(const float4*)(b_fp + l * 64 + c0);
        __syncthreads();

        // GEMM: h[r][c] = relu( sum_k v[r][k] * Wt[k][c] + b[c] )
        float acc[8][4];
#pragma unroll
        for (int i = 0; i < 8; i++)
#pragma unroll
            for (int c = 0; c < 4; c++) acc[i][c] = bias[c];

#pragma unroll 2
        for (int k = 0; k < 64; k += 4) {
            float wreg[4][4];
            *(float4*)wreg[0] = *(const float4*)&w_sh[(k + 0) * 64 + c0];
            *(float4*)wreg[1] = *(const float4*)&w_sh[(k + 1) * 64 + c0];
            *(float4*)wreg[2] = *(const float4*)&w_sh[(k + 2) * 64 + c0];
            *(float4*)wreg[3] = *(const float4*)&w_sh[(k + 3) * 64 + c0];
#pragma unroll
            for (int i = 0; i < 8; i++) {
                float vreg[4];
                *(float4*)vreg = *(const float4*)&v_sh[(r0 + i) * 64 + k];
#pragma unroll
                for (int kk = 0; kk < 4; kk++)
#pragma unroll
                    for (int c = 0; c < 4; c++)
                        acc[i][c] = fmaf(vreg[kk], wreg[kk][c], acc[i][c]);
            }
        }
#pragma unroll
        for (int i = 0; i < 8; i++) {
            float4 hv;
            hv.x = fmaxf(acc[i][0], 0.f);
            hv.y = fmaxf(acc[i][1], 0.f);
            hv.z = fmaxf(acc[i][2], 0.f);
            hv.w = fmaxf(acc[i][3], 0.f);
            *(float4*)&h_sh[(r0 + i) * 64 + c0] = hv;
        }
        __syncthreads();

        // aggregation: v2[d] = h[d] + sum_{s in nbr(d)} h[s]   (CSR by dst)
        for (int r = rg; r < GA; r += 4) {
            int n = atomBase + r;
            unsigned lo = g_off[n], hi = g_off[n + 1];
            int mb = (r / S) * S;
            float a = h_sh[r * 64 + tj];
            for (unsigned e = lo; e < hi; e++) {
                int ls = g_csr[e];
                a += h_sh[(mb + ls) * 64 + tj];
            }
            v_sh[r * 64 + tj] = a;
        }
        __syncthreads();

        // row L2 norms
        for (int r = warp; r < GA; r += 8) {
            float x = v_sh[r * 64 + lane];
            float y = v_sh[r * 64 + 32 + lane];
            float s = x * x + y * y;
#pragma unroll
            for (int o = 16; o; o >>= 1) s += __shfl_xor_sync(0xffffffffu, s, o);
            if (lane == 0) inv_sh[r] = 1.0f / fmaxf(sqrtf(s), 1e-12f);
        }
        __syncthreads();
        for (int r = rg; r < GA; r += 4) v_sh[r * 64 + tj] *= inv_sh[r];
    }
    __syncthreads();

    // ---- molecule sums into h_sh[0..Ga*64) ----
    for (int m = rg; m < Ga; m += 4) {
        float s = 0.f;
        for (int i = 0; i < S; i++) s += v_sh[(m * S + i) * 64 + tj];
        h_sh[m * 64 + tj] = s;
    }

    // ---- output MLP (per molecule) ----
    float* cur = h_sh;
    float* nxt = v_sh;
    for (int l = 0; l < LO; l++) {
        __syncthreads();
        {
            const float4* ws = (const float4*)(g_Wt + (LH + l) * 4096);
            float4* wd = (float4*)w_sh;
            for (int i = t; i < 1024; i += 256) wd[i] = ws[i];
        }
        __syncthreads();
        for (int m = rg; m < Ga; m += 4) {
            float a = b_out[l * 64 + tj];
#pragma unroll 8
            for (int k = 0; k < 64; k++)
                a = fmaf(cur[m * 64 + k], w_sh[k * 64 + tj], a);
            nxt[m * 64 + tj] = fmaxf(a, 0.f);
        }
        float* tmp = cur; cur = nxt; nxt = tmp;
    }
    __syncthreads();

    // ---- final dot with W_prop + b_prop ----
    for (int m = warp; m < Ga; m += 8) {
        float s = cur[m * 64 + lane] * wprop[lane]
                + cur[m * 64 + 32 + lane] * wprop[32 + lane];
#pragma unroll
        for (int o = 16; o; o >>= 1) s += __shfl_xor_sync(0xffffffffu, s, o);
        if (lane == 0) out[molBase + m] = s + bprop[0];
    }
}

// ---------------------------------------------------------------------------

extern "C" void kernel_launch(void* const* d_in, const int* in_sizes, int n_in,
                              void* d_out, int out_size) {
    const float* emb    = (const float*)d_in[0];
    const float* W_fp   = (const float*)d_in[1];
    const float* b_fp   = (const float*)d_in[2];
    const float* W_out  = (const float*)d_in[3];
    const float* b_out  = (const float*)d_in[4];
    const float* W_prop = (const float*)d_in[5];
    const float* b_prop = (const float*)d_in[6];
    const int*   fp     = (const int*)d_in[7];
    const int*   esrc   = (const int*)d_in[8];
    const int*   edst   = (const int*)d_in[9];
    // d_in[10] = node_mol (implied by uniform blocks), d_in[11] = num_mols (unused)

    float* out = (float*)d_out;

    const int M  = out_size;            // output is [M, 1]
    const int T  = in_sizes[7];
    const int E  = in_sizes[8];
    const int LH = in_sizes[2] / 64;    // b_fp = [LH, 64]
    const int LO = in_sizes[4] / 64;    // b_out = [LO, 64]
    const int S  = T / M;               // atoms per molecule (uniform blocks)
    int G = TILE_ROWS / S;              // molecules per CTA
    if (G < 1) G = 1;

    const int ZB = (T + 255) / 256;
    const int EB = (E + 255) / 256;
    const int NB1 = (T + 1023) / 1024;

    // ---- build CSR (by dst) ----
    zero_kernel<<<ZB, 256>>>(T);
    hist_kernel<<<EB, 256>>>(edst, E);
    scan1_kernel<<<NB1, 256>>>(T);
    scan2_kernel<<<1, 256>>>(NB1);
    scan3_kernel<<<NB1, 256>>>(T, E);
    scatter_kernel<<<EB, 256>>>(esrc, edst, E, S);

    // ---- transpose weights ----
    wtrans_kernel<<<LH + LO, 256>>>(W_fp, W_out, LH);

    // ---- fused GNN ----
    const int smemBytes = (8192 + 8192 + 4096 + 128) * sizeof(float); // 82432
    cudaFuncSetAttribute(gnn_fused_kernel,
                         cudaFuncAttributeMaxDynamicSharedMemorySize, smemBytes);
    const int nBlocks = (M + G - 1) / G;
    gnn_fused_kernel<<<nBlocks, 256, smemBytes>>>(fp, emb, b_fp, b_out,
                                                  W_prop, b_prop, out,
                                                  S, G, M, LH, LO);
}

// round 2
// speedup vs baseline: 1.3070x; 1.3070x over previous
#include <cuda_runtime.h>
#include <cuda_bf16.h>
#include <math.h>

// ---------------------------------------------------------------------------
// MolecularGNN fully fused: embed -> LH gnn layers -> mol sum -> MLP -> out.
// Block-diagonal per molecule => one CTA handles 128 atom rows end-to-end.
// R1 changes: f32x2 packed FMA GEMM, slot-array adjacency (no scans),
// smem-staged adjacency, batched-shfl norms.
// ---------------------------------------------------------------------------

#define MAX_T   524288
#define MAX_LAY 8
#define CAP     32          // adjacency slots per node (Poisson(4), max ~19)
#define TILE_ROWS 128

__device__ unsigned      g_cnt[MAX_T];
__device__ unsigned char g_slots[(size_t)MAX_T * CAP];   // local src idx per edge
__device__ float         g_Wt[MAX_LAY * 4096];           // transposed 64x64 weights

typedef unsigned long long u64;
__device__ __forceinline__ u64 pk2(float x, float y) {
    u64 r; asm("mov.b64 %0,{%1,%2};" : "=l"(r) : "f"(x), "f"(y)); return r;
}
__device__ __forceinline__ u64 bc2(float x) { return pk2(x, x); }
__device__ __forceinline__ void fma2(u64& d, u64 a, u64 b) {
    asm("fma.rn.f32x2 %0,%1,%2,%3;" : "=l"(d) : "l"(a), "l"(b), "l"(d));
}
__device__ __forceinline__ void up2(u64 v, float& x, float& y) {
    asm("mov.b64 {%0,%1},%2;" : "=f"(x), "=f"(y) : "l"(v));
}

// ---------------------------------------------------------------------------
// init: transpose weights (blocks 0..LH+LO-1) and zero per-node counters
__global__ void init_kernel(const float* __restrict__ Wfp,
                            const float* __restrict__ Wout,
                            int LH, int LO, int T) {
    int b = blockIdx.x;
    int NW = LH + LO;
    if (b < NW) {
        const float* Ws = (b < LH) ? (Wfp + b * 4096) : (Wout + (b - LH) * 4096);
        float* o = g_Wt + b * 4096;
        for (int i = threadIdx.x; i < 4096; i += blockDim.x) {
            int k = i >> 6, j = i & 63;
            o[i] = Ws[j * 64 + k];          // Wt[k][j] = W[j][k]
        }
    } else {
        int i = (b - NW) * 256 + threadIdx.x;
        if (i < T) g_cnt[i] = 0u;
    }
}

// scatter edges into fixed-capacity slot lists (by dst), storing LOCAL src idx
__global__ void scatter_kernel(const int* __restrict__ src,
                               const int* __restrict__ dst, int E, int S) {
    int e = blockIdx.x * blockDim.x + threadIdx.x;
    if (e < E) {
        int d = dst[e];
        unsigned idx = atomicAdd(&g_cnt[d], 1u);
        if (idx < CAP) {
            int s = src[e];
            g_slots[(size_t)d * CAP + idx] = (unsigned char)(s - (s / S) * S);
        }
    }
}

// ---------------------------------------------------------------------------
// Fused kernel. One CTA: G molecules (G*S <= 128 rows). 256 threads.
// smem floats: v[8192] h[8192] w[4096] inv[128] cnt[128] slots[1024] mb[32]
// ---------------------------------------------------------------------------
__global__ __launch_bounds__(256, 2)
void gnn_fused_kernel(const int* __restrict__ fp,
                      const float* __restrict__ emb,
                      const float* __restrict__ b_fp,
                      const float* __restrict__ b_out,
                      const float* __restrict__ wprop,
                      const float* __restrict__ bprop,
                      const int* __restrict__ esrc,
                      const int* __restrict__ edst,
                      float* __restrict__ out,
                      int S, int G, int M, int E, int LH, int LO) {
    extern __shared__ float sm[];
    float* v_sh   = sm;                         // 8192 f
    float* h_sh   = sm + 8192;                  // 8192 f
    float* w_sh   = sm + 16384;                 // 4096 f
    float* inv_sh = sm + 20480;                 // 128 f
    unsigned* cnt_sh = (unsigned*)(sm + 20608); // 128 u32
    unsigned char* slot_sh = (unsigned char*)(sm + 20736); // 4096 B
    unsigned char* mb_sh   = (unsigned char*)(sm + 21760); // 128 B

    const int t = threadIdx.x;
    const int molBase = blockIdx.x * G;
    const int Ga = min(G, M - molBase);
    if (Ga <= 0) return;
    const int GA = Ga * S;
    const int atomBase = molBase * S;

    const int tc = t & 15, trg = t >> 4;        // gemm: 16 cols x 16 rowgroups
    const int c0 = tc * 4, r0 = trg * 8;
    const int tj = t & 63, rg = t >> 6;         // agg: 64 cols x 4 rowgroups
    const int warp = t >> 5, lane = t & 31;

    // ---- stage adjacency (constant across layers) + mol-base table ----
    {
        const u64* gs = (const u64*)(g_slots + (size_t)atomBase * CAP);
        u64* ss = (u64*)slot_sh;
        const int nQ = (GA * CAP) >> 3;
        for (int i = t; i < nQ; i += 256) ss[i] = gs[i];
        for (int r = t; r < GA; r += 256) cnt_sh[r] = g_cnt[atomBase + r];
        for (int r = t; r < TILE_ROWS; r += 256)
            mb_sh[r] = (unsigned char)((r / S) * S);
    }

    // ---- load embeddings (padded rows zeroed) ----
    for (int idx = t; idx < GA * 64; idx += 256) {
        int r = idx >> 6, j = idx & 63;
        v_sh[idx] = emb[fp[atomBase + r] * 64 + j];
    }
    for (int idx = GA * 64 + t; idx < TILE_ROWS * 64; idx += 256) v_sh[idx] = 0.f;

    // ---- GNN layers ----
    for (int l = 0; l < LH; l++) {
        __syncthreads();
        {
            const float4* ws = (const float4*)(g_Wt + l * 4096);
            float4* wd = (float4*)w_sh;
            for (int i = t; i < 1024; i += 256) wd[i] = ws[i];
        }
        float4 bv = *(const float4*)(b_fp + l * 64 + c0);
        __syncthreads();

        // GEMM: h = relu(v @ Wt + b), packed f32x2 over column pairs
        u64 acc[8][2];
        {
            u64 b01 = pk2(bv.x, bv.y), b23 = pk2(bv.z, bv.w);
#pragma unroll
            for (int i = 0; i < 8; i++) { acc[i][0] = b01; acc[i][1] = b23; }
        }
#pragma unroll 2
        for (int k = 0; k < 64; k += 4) {
            u64 wp[4][2];
#pragma unroll
            for (int kk = 0; kk < 4; kk++) {
                float4 wf = *(const float4*)&w_sh[(k + kk) * 64 + c0];
                wp[kk][0] = pk2(wf.x, wf.y);
                wp[kk][1] = pk2(wf.z, wf.w);
            }
#pragma unroll
            for (int i = 0; i < 8; i++) {
                float4 vf = *(const float4*)&v_sh[(r0 + i) * 64 + k];
                u64 v0 = bc2(vf.x), v1 = bc2(vf.y), v2 = bc2(vf.z), v3 = bc2(vf.w);
                fma2(acc[i][0], v0, wp[0][0]); fma2(acc[i][1], v0, wp[0][1]);
                fma2(acc[i][0], v1, wp[1][0]); fma2(acc[i][1], v1, wp[1][1]);
                fma2(acc[i][0], v2, wp[2][0]); fma2(acc[i][1], v2, wp[2][1]);
                fma2(acc[i][0], v3, wp[3][0]); fma2(acc[i][1], v3, wp[3][1]);
            }
        }
#pragma unroll
        for (int i = 0; i < 8; i++) {
            float4 hv;
            up2(acc[i][0], hv.x, hv.y);
            up2(acc[i][1], hv.z, hv.w);
            hv.x = fmaxf(hv.x, 0.f); hv.y = fmaxf(hv.y, 0.f);
            hv.z = fmaxf(hv.z, 0.f); hv.w = fmaxf(hv.w, 0.f);
            *(float4*)&h_sh[(r0 + i) * 64 + c0] = hv;
        }
        __syncthreads();

        // aggregation: v[d] = h[d] + sum_{s in nbr(d)} h[s]
        for (int r = rg; r < GA; r += 4) {
            unsigned c = cnt_sh[r];
            int mb = mb_sh[r];
            float a = h_sh[r * 64 + tj];
            if (c <= CAP) {
                const unsigned char* sl = slot_sh + r * CAP;
                for (unsigned e = 0; e < c; e++)
                    a += h_sh[(mb + sl[e]) * 64 + tj];
            } else {
                // never taken for Poisson(4) degrees; correctness fallback
                int n = atomBase + r;
                for (int e = 0; e < E; e++)
                    if (edst[e] == n) {
                        int s = esrc[e];
                        a += h_sh[(mb + (s - (s / S) * S)) * 64 + tj];
                    }
            }
            v_sh[r * 64 + tj] = a;
        }
        __syncthreads();

        // row L2 norms: 16 interleaved warp reductions (rows are padded w/ 0s)
        {
            float sq[16];
            const int base = warp * 16;
#pragma unroll
            for (int i = 0; i < 16; i++) {
                float x = v_sh[(base + i) * 64 + lane];
                float y = v_sh[(base + i) * 64 + 32 + lane];
                sq[i] = x * x + y * y;
            }
#pragma unroll
            for (int o = 16; o; o >>= 1)
#pragma unroll
                for (int i = 0; i < 16; i++)
                    sq[i] += __shfl_xor_sync(0xffffffffu, sq[i], o);
#pragma unroll
            for (int i = 0; i < 16; i++)
                if (lane == i)
                    inv_sh[base + i] = rsqrtf(fmaxf(sq[i], 1e-24f));
        }
        __syncthreads();
        for (int r = rg; r < GA; r += 4) v_sh[r * 64 + tj] *= inv_sh[r];
    }
    __syncthreads();

    // ---- molecule sums ----
    for (int m = rg; m < Ga; m += 4) {
        float s = 0.f;
        for (int i = 0; i < S; i++) s += v_sh[(m * S + i) * 64 + tj];
        h_sh[m * 64 + tj] = s;
    }

    // ---- output MLP ----
    float* cur = h_sh;
    float* nxt = v_sh;
    for (int l = 0; l < LO; l++) {
        __syncthreads();
        {
            const float4* ws = (const float4*)(g_Wt + (LH + l) * 4096);
            float4* wd = (float4*)w_sh;
            for (int i = t; i < 1024; i += 256) wd[i] = ws[i];
        }
        __syncthreads();
        for (int m = rg; m < Ga; m += 4) {
            float a = b_out[l * 64 + tj];
#pragma unroll 8
            for (int k = 0; k < 64; k++)
                a = fmaf(cur[m * 64 + k], w_sh[k * 64 + tj], a);
            nxt[m * 64 + tj] = fmaxf(a, 0.f);
        }
        float* tmp = cur; cur = nxt; nxt = tmp;
    }
    __syncthreads();

    // ---- final dot ----
    for (int m = warp; m < Ga; m += 8) {
        float s = cur[m * 64 + lane] * wprop[lane]
                + cur[m * 64 + 32 + lane] * wprop[32 + lane];
#pragma unroll
        for (int o = 16; o; o >>= 1) s += __shfl_xor_sync(0xffffffffu, s, o);
        if (lane == 0) out[molBase + m] = s + bprop[0];
    }
}

// ---------------------------------------------------------------------------

extern "C" void kernel_launch(void* const* d_in, const int* in_sizes, int n_in,
                              void* d_out, int out_size) {
    const float* emb    = (const float*)d_in[0];
    const float* W_fp   = (const float*)d_in[1];
    const float* b_fp   = (const float*)d_in[2];
    const float* W_out  = (const float*)d_in[3];
    const float* b_out  = (const float*)d_in[4];
    const float* W_prop = (const float*)d_in[5];
    const float* b_prop = (const float*)d_in[6];
    const int*   fp     = (const int*)d_in[7];
    const int*   esrc   = (const int*)d_in[8];
    const int*   edst   = (const int*)d_in[9];

    float* out = (float*)d_out;

    const int M  = out_size;
    const int T  = in_sizes[7];
    const int E  = in_sizes[8];
    const int LH = in_sizes[2] / 64;
    const int LO = in_sizes[4] / 64;
    const int S  = T / M;
    int G = TILE_ROWS / S;
    if (G < 1) G = 1;

    const int NW = LH + LO;
    const int ZB = (T + 255) / 256;
    init_kernel<<<NW + ZB, 256>>>(W_fp, W_out, LH, LO, T);
    scatter_kernel<<<(E + 255) / 256, 256>>>(esrc, edst, E, S);

    const int smemBytes = 21760 * 4 + 128;      // 87168 B
    cudaFuncSetAttribute(gnn_fused_kernel,
                         cudaFuncAttributeMaxDynamicSharedMemorySize, smemBytes);
    const int nBlocks = (M + G - 1) / G;
    gnn_fused_kernel<<<nBlocks, 256, smemBytes>>>(fp, emb, b_fp, b_out,
                                                  W_prop, b_prop, esrc, edst, out,
                                                  S, G, M, E, LH, LO);
}